// round 8
// baseline (speedup 1.0000x reference)
#include <cuda_runtime.h>

// Polar decomposition of A = rotation[n] @ mat. 2 matrices/thread packed in
// f32x2 (FFMA2). Det-scaled Newton:
//   X <- 0.5*g*X + 0.5*g^2*sign(det)*cof(X),  g = |det X|^(-1/3)
// Load: smem-staged coalesced. Store: DIRECT from registers (no barrier) so
// each warp retires as soon as its own 64 matrices converge.

#define TPB 256
typedef unsigned long long u64;

__device__ __forceinline__ u64 f2pack(float lo, float hi) {
    u64 r; asm("mov.b64 %0, {%1, %2};" : "=l"(r) : "f"(lo), "f"(hi)); return r;
}
__device__ __forceinline__ void f2unpack(u64 v, float& lo, float& hi) {
    asm("mov.b64 {%0, %1}, %2;" : "=f"(lo), "=f"(hi) : "l"(v));
}
__device__ __forceinline__ u64 f2mul(u64 a, u64 b) {
    u64 d; asm("mul.rn.f32x2 %0, %1, %2;" : "=l"(d) : "l"(a), "l"(b)); return d;
}
__device__ __forceinline__ u64 f2fma(u64 a, u64 b, u64 c) {
    u64 d; asm("fma.rn.f32x2 %0, %1, %2, %3;" : "=l"(d) : "l"(a), "l"(b), "l"(c)); return d;
}
__device__ __forceinline__ u64 f2neg(u64 a) { return a ^ 0x8000000080000000ULL; }
__device__ __forceinline__ u64 f2msub(u64 a, u64 b, u64 c, u64 d) {
    return f2fma(a, b, f2neg(f2mul(c, d)));
}
__device__ __forceinline__ float lg2_fast(float x) {
    float r; asm("lg2.approx.f32 %0, %1;" : "=f"(r) : "f"(x)); return r;
}
__device__ __forceinline__ float ex2_fast(float x) {
    float r; asm("ex2.approx.f32 %0, %1;" : "=f"(r) : "f"(x)); return r;
}

struct P2 { u64 x0,x1,x2,x3,x4,x5,x6,x7,x8; };

// One det-scaled Newton step (rcp-free): det(gX) = sign(det) exactly.
__device__ __forceinline__ void newton_step(P2& X) {
    const u64 c00 = f2msub(X.x4, X.x8, X.x5, X.x7);
    const u64 c01 = f2msub(X.x5, X.x6, X.x3, X.x8);
    const u64 c02 = f2msub(X.x3, X.x7, X.x4, X.x6);
    const u64 c10 = f2msub(X.x2, X.x7, X.x1, X.x8);
    const u64 c11 = f2msub(X.x0, X.x8, X.x2, X.x6);
    const u64 c12 = f2msub(X.x1, X.x6, X.x0, X.x7);
    const u64 c20 = f2msub(X.x1, X.x5, X.x2, X.x4);
    const u64 c21 = f2msub(X.x2, X.x3, X.x0, X.x5);
    const u64 c22 = f2msub(X.x0, X.x4, X.x1, X.x3);
    const u64 det = f2fma(X.x0, c00, f2fma(X.x1, c01, f2mul(X.x2, c02)));

    float dl, dh;
    f2unpack(det, dl, dh);
    const float gl = ex2_fast(-0.33333333f * lg2_fast(fmaxf(fabsf(dl), 1e-36f)));
    const float gh = ex2_fast(-0.33333333f * lg2_fast(fmaxf(fabsf(dh), 1e-36f)));
    const float rl = copysignf(0.5f * gl * gl, dl);   // 0.5/(g*det) exactly
    const float rh = copysignf(0.5f * gh * gh, dh);
    const u64 hg = f2pack(0.5f * gl, 0.5f * gh);
    const u64 rr = f2pack(rl, rh);

    X.x0 = f2fma(rr, c00, f2mul(hg, X.x0));
    X.x1 = f2fma(rr, c01, f2mul(hg, X.x1));
    X.x2 = f2fma(rr, c02, f2mul(hg, X.x2));
    X.x3 = f2fma(rr, c10, f2mul(hg, X.x3));
    X.x4 = f2fma(rr, c11, f2mul(hg, X.x4));
    X.x5 = f2fma(rr, c12, f2mul(hg, X.x5));
    X.x6 = f2fma(rr, c20, f2mul(hg, X.x6));
    X.x7 = f2fma(rr, c21, f2mul(hg, X.x7));
    X.x8 = f2fma(rr, c22, f2mul(hg, X.x8));
}

__global__ void __launch_bounds__(TPB)
polar2d_kernel(const float* __restrict__ rot,
               const float* __restrict__ mat,
               float* __restrict__ out,
               float* __restrict__ logdet,
               int N)
{
    __shared__ float s[TPB * 18];
    const int tid  = threadIdx.x;
    const int base = blockIdx.x * (TPB * 2);
    const int nmat = min(TPB * 2, N - base);
    const int nflt = nmat * 9;

    // ---- cooperative coalesced load: global -> smem ----
    {
        const float* g = rot + (size_t)base * 9;
        const int nv = nflt >> 2;
        const float4* g4 = reinterpret_cast<const float4*>(g);
        float4* s4 = reinterpret_cast<float4*>(s);
        for (int i = tid; i < nv; i += TPB) s4[i] = g4[i];
        for (int i = (nv << 2) + tid; i < nflt; i += TPB) s[i] = g[i];
    }

    const float m0 = __ldg(mat + 0), m1 = __ldg(mat + 1), m2 = __ldg(mat + 2);
    const float m3 = __ldg(mat + 3), m4 = __ldg(mat + 4), m5 = __ldg(mat + 5);
    const float m6 = __ldg(mat + 6), m7 = __ldg(mat + 7), m8 = __ldg(mat + 8);
    __syncthreads();   // the ONLY barrier: load staging complete

    const int  gm  = base + 2 * tid;       // first of this thread's 2 matrices
    const bool vlo = gm     < N;
    const bool vhi = gm + 1 < N;

    u64 R[9];
    {
        const int olo = 2 * tid * 9, ohi = olo + 9;
        #pragma unroll
        for (int k = 0; k < 9; ++k) {
            const float idv = (k == 0 || k == 4 || k == 8) ? 1.0f : 0.0f;
            const float a = vlo ? s[olo + k] : idv;
            const float b = vhi ? s[ohi + k] : idv;
            R[k] = f2pack(a, b);
        }
    }

    const u64 M0 = f2pack(m0, m0), M1 = f2pack(m1, m1), M2 = f2pack(m2, m2);
    const u64 M3 = f2pack(m3, m3), M4 = f2pack(m4, m4), M5 = f2pack(m5, m5);
    const u64 M6 = f2pack(m6, m6), M7 = f2pack(m7, m7), M8 = f2pack(m8, m8);

    P2 X;
    X.x0 = f2fma(R[0], M0, f2fma(R[1], M3, f2mul(R[2], M6)));
    X.x1 = f2fma(R[0], M1, f2fma(R[1], M4, f2mul(R[2], M7)));
    X.x2 = f2fma(R[0], M2, f2fma(R[1], M5, f2mul(R[2], M8)));
    X.x3 = f2fma(R[3], M0, f2fma(R[4], M3, f2mul(R[5], M6)));
    X.x4 = f2fma(R[3], M1, f2fma(R[4], M4, f2mul(R[5], M7)));
    X.x5 = f2fma(R[3], M2, f2fma(R[4], M5, f2mul(R[5], M8)));
    X.x6 = f2fma(R[6], M0, f2fma(R[7], M3, f2mul(R[8], M6)));
    X.x7 = f2fma(R[6], M1, f2fma(R[7], M4, f2mul(R[8], M7)));
    X.x8 = f2fma(R[6], M2, f2fma(R[7], M5, f2mul(R[8], M8)));

    // ---- head: 4 unrolled det-scaled steps, no checks ----
    #pragma unroll
    for (int it = 0; it < 4; ++it) newton_step(X);

    // ---- adaptive tail with per-warp early exit ----
    #pragma unroll 1
    for (int it = 0; it < 8; ++it) {
        u64 fro = f2mul(X.x0, X.x0);
        fro = f2fma(X.x1, X.x1, fro); fro = f2fma(X.x2, X.x2, fro);
        fro = f2fma(X.x3, X.x3, fro); fro = f2fma(X.x4, X.x4, fro);
        fro = f2fma(X.x5, X.x5, fro); fro = f2fma(X.x6, X.x6, fro);
        fro = f2fma(X.x7, X.x7, fro); fro = f2fma(X.x8, X.x8, fro);
        float fl, fh;
        f2unpack(fro, fl, fh);
        const bool ok = (fabsf(fl - 3.0f) < 2.5e-4f) && (fabsf(fh - 3.0f) < 2.5e-4f);
        if (__all_sync(0xffffffffu, ok)) break;
        newton_step(X);
    }

    // ---- DIRECT store from registers: 9x STG.64 per thread, no barrier ----
    // Thread's 72-byte record is always 8-aligned (out + gm*9*4, gm even).
    {
        float a, b;
        float2* p = reinterpret_cast<float2*>(out + (size_t)gm * 9);
        if (vlo && vhi) {
            f2unpack(X.x0, a, b); float t0 = a; float h0 = b;   // save hi-lane
            float lo[9], hi[9];
            f2unpack(X.x0, lo[0], hi[0]); f2unpack(X.x1, lo[1], hi[1]);
            f2unpack(X.x2, lo[2], hi[2]); f2unpack(X.x3, lo[3], hi[3]);
            f2unpack(X.x4, lo[4], hi[4]); f2unpack(X.x5, lo[5], hi[5]);
            f2unpack(X.x6, lo[6], hi[6]); f2unpack(X.x7, lo[7], hi[7]);
            f2unpack(X.x8, lo[8], hi[8]);
            (void)t0; (void)h0;
            p[0] = make_float2(lo[0], lo[1]);
            p[1] = make_float2(lo[2], lo[3]);
            p[2] = make_float2(lo[4], lo[5]);
            p[3] = make_float2(lo[6], lo[7]);
            p[4] = make_float2(lo[8], hi[0]);
            p[5] = make_float2(hi[1], hi[2]);
            p[6] = make_float2(hi[3], hi[4]);
            p[7] = make_float2(hi[5], hi[6]);
            p[8] = make_float2(hi[7], hi[8]);
            *reinterpret_cast<float2*>(logdet + gm) = make_float2(0.f, 0.f);
        } else if (vlo) {
            float lo[9], dummy;
            f2unpack(X.x0, lo[0], dummy); f2unpack(X.x1, lo[1], dummy);
            f2unpack(X.x2, lo[2], dummy); f2unpack(X.x3, lo[3], dummy);
            f2unpack(X.x4, lo[4], dummy); f2unpack(X.x5, lo[5], dummy);
            f2unpack(X.x6, lo[6], dummy); f2unpack(X.x7, lo[7], dummy);
            f2unpack(X.x8, lo[8], dummy);
            float* q = out + (size_t)gm * 9;
            #pragma unroll
            for (int k = 0; k < 9; ++k) q[k] = lo[k];
            logdet[gm] = 0.0f;
        }
    }
}

__global__ void zero_tail_kernel(float* __restrict__ p, long long n)
{
    long long i = (long long)blockIdx.x * blockDim.x + threadIdx.x;
    if (i < n) p[i] = 0.0f;
}

extern "C" void kernel_launch(void* const* d_in, const int* in_sizes, int n_in,
                              void* d_out, int out_size)
{
    const float* rot = (const float*)d_in[0];
    const float* mat = (const float*)d_in[1];
    float* out = (float*)d_out;

    const int N = in_sizes[0] / 9;
    float* logdet = out + (size_t)N * 9;

    const int mats_per_block = TPB * 2;
    const int blocks = (N + mats_per_block - 1) / mats_per_block;
    polar2d_kernel<<<blocks, TPB>>>(rot, mat, out, logdet, N);

    const long long used = 10LL * N;
    if ((long long)out_size > used) {
        const long long extra = (long long)out_size - used;
        const int zb = (int)((extra + 255) / 256);
        zero_tail_kernel<<<zb, 256>>>(out + used, extra);
    }
}

// round 9
// speedup vs baseline: 1.4232x; 1.4232x over previous
#include <cuda_runtime.h>

// Polar decomposition of A = rotation[n] @ mat. 2 matrices/thread packed in
// f32x2 (FFMA2), smem-staged coalesced I/O both directions (R8 showed direct
// 72B-stride stores are catastrophic).
//  head: 4 det-scaled Newton steps  X <- 0.5*g*X + 0.5*g^2*sign(det)*cof(X)
//  tail: unscaled Newton X <- 0.5*(X + X^-T) via one rcp.approx (short chain),
//        step-pairs per convergence check.

#define TPB 256
typedef unsigned long long u64;

__device__ __forceinline__ u64 f2pack(float lo, float hi) {
    u64 r; asm("mov.b64 %0, {%1, %2};" : "=l"(r) : "f"(lo), "f"(hi)); return r;
}
__device__ __forceinline__ void f2unpack(u64 v, float& lo, float& hi) {
    asm("mov.b64 {%0, %1}, %2;" : "=f"(lo), "=f"(hi) : "l"(v));
}
__device__ __forceinline__ u64 f2mul(u64 a, u64 b) {
    u64 d; asm("mul.rn.f32x2 %0, %1, %2;" : "=l"(d) : "l"(a), "l"(b)); return d;
}
__device__ __forceinline__ u64 f2fma(u64 a, u64 b, u64 c) {
    u64 d; asm("fma.rn.f32x2 %0, %1, %2, %3;" : "=l"(d) : "l"(a), "l"(b), "l"(c)); return d;
}
__device__ __forceinline__ u64 f2neg(u64 a) { return a ^ 0x8000000080000000ULL; }
__device__ __forceinline__ u64 f2msub(u64 a, u64 b, u64 c, u64 d) {
    return f2fma(a, b, f2neg(f2mul(c, d)));
}
__device__ __forceinline__ float lg2_fast(float x) {
    float r; asm("lg2.approx.f32 %0, %1;" : "=f"(r) : "f"(x)); return r;
}
__device__ __forceinline__ float ex2_fast(float x) {
    float r; asm("ex2.approx.f32 %0, %1;" : "=f"(r) : "f"(x)); return r;
}
__device__ __forceinline__ float rcp_fast(float x) {
    float r; asm("rcp.approx.f32 %0, %1;" : "=f"(r) : "f"(x)); return r;
}

struct P2 { u64 x0,x1,x2,x3,x4,x5,x6,x7,x8; };

// cofactors + det (shared by both step types)
__device__ __forceinline__ void cof_det(const P2& X, u64 C[9], u64& det) {
    C[0] = f2msub(X.x4, X.x8, X.x5, X.x7);
    C[1] = f2msub(X.x5, X.x6, X.x3, X.x8);
    C[2] = f2msub(X.x3, X.x7, X.x4, X.x6);
    C[3] = f2msub(X.x2, X.x7, X.x1, X.x8);
    C[4] = f2msub(X.x0, X.x8, X.x2, X.x6);
    C[5] = f2msub(X.x1, X.x6, X.x0, X.x7);
    C[6] = f2msub(X.x1, X.x5, X.x2, X.x4);
    C[7] = f2msub(X.x2, X.x3, X.x0, X.x5);
    C[8] = f2msub(X.x0, X.x4, X.x1, X.x3);
    det  = f2fma(X.x0, C[0], f2fma(X.x1, C[1], f2mul(X.x2, C[2])));
}

__device__ __forceinline__ void apply(P2& X, const u64 C[9], u64 hg, u64 rr) {
    X.x0 = f2fma(rr, C[0], f2mul(hg, X.x0));
    X.x1 = f2fma(rr, C[1], f2mul(hg, X.x1));
    X.x2 = f2fma(rr, C[2], f2mul(hg, X.x2));
    X.x3 = f2fma(rr, C[3], f2mul(hg, X.x3));
    X.x4 = f2fma(rr, C[4], f2mul(hg, X.x4));
    X.x5 = f2fma(rr, C[5], f2mul(hg, X.x5));
    X.x6 = f2fma(rr, C[6], f2mul(hg, X.x6));
    X.x7 = f2fma(rr, C[7], f2mul(hg, X.x7));
    X.x8 = f2fma(rr, C[8], f2mul(hg, X.x8));
}

// Det-scaled Newton (head): g = |det|^(-1/3); 0.5/(g det) = 0.5 g^2 sign(det).
__device__ __forceinline__ void newton_scaled(P2& X) {
    u64 C[9], det;
    cof_det(X, C, det);
    float dl, dh;
    f2unpack(det, dl, dh);
    const float gl = ex2_fast(-0.33333333f * lg2_fast(fmaxf(fabsf(dl), 1e-36f)));
    const float gh = ex2_fast(-0.33333333f * lg2_fast(fmaxf(fabsf(dh), 1e-36f)));
    const float rl = copysignf(0.5f * gl * gl, dl);
    const float rh = copysignf(0.5f * gh * gh, dh);
    apply(X, C, f2pack(0.5f * gl, 0.5f * gh), f2pack(rl, rh));
}

// Unscaled Newton (tail): X <- 0.5*X + (0.5/det)*cof(X). One MUFU per lane.
__device__ __forceinline__ void newton_plain(P2& X) {
    u64 C[9], det;
    cof_det(X, C, det);
    float dl, dh;
    f2unpack(det, dl, dh);
    const float rl = 0.5f * rcp_fast(dl);
    const float rh = 0.5f * rcp_fast(dh);
    apply(X, C, 0x3F0000003F000000ULL /* (0.5f,0.5f) */, f2pack(rl, rh));
}

__global__ void __launch_bounds__(TPB, 6)
polar2r_kernel(const float* __restrict__ rot,
               const float* __restrict__ mat,
               float* __restrict__ out,
               float* __restrict__ logdet,
               int N)
{
    __shared__ float s[TPB * 18];
    const int tid  = threadIdx.x;
    const int base = blockIdx.x * (TPB * 2);
    const int nmat = min(TPB * 2, N - base);
    const int nflt = nmat * 9;

    // ---- cooperative coalesced load: global -> smem ----
    {
        const float* g = rot + (size_t)base * 9;
        const int nv = nflt >> 2;
        const float4* g4 = reinterpret_cast<const float4*>(g);
        float4* s4 = reinterpret_cast<float4*>(s);
        for (int i = tid; i < nv; i += TPB) s4[i] = g4[i];
        for (int i = (nv << 2) + tid; i < nflt; i += TPB) s[i] = g[i];
    }

    const float m0 = __ldg(mat + 0), m1 = __ldg(mat + 1), m2 = __ldg(mat + 2);
    const float m3 = __ldg(mat + 3), m4 = __ldg(mat + 4), m5 = __ldg(mat + 5);
    const float m6 = __ldg(mat + 6), m7 = __ldg(mat + 7), m8 = __ldg(mat + 8);
    __syncthreads();

    const bool vlo = (base + 2 * tid)     < N;
    const bool vhi = (base + 2 * tid + 1) < N;

    u64 R[9];
    {
        const int olo = 2 * tid * 9, ohi = olo + 9;
        #pragma unroll
        for (int k = 0; k < 9; ++k) {
            const float idv = (k == 0 || k == 4 || k == 8) ? 1.0f : 0.0f;
            const float a = vlo ? s[olo + k] : idv;
            const float b = vhi ? s[ohi + k] : idv;
            R[k] = f2pack(a, b);
        }
    }
    __syncthreads();   // smem reused for store staging

    const u64 M0 = f2pack(m0, m0), M1 = f2pack(m1, m1), M2 = f2pack(m2, m2);
    const u64 M3 = f2pack(m3, m3), M4 = f2pack(m4, m4), M5 = f2pack(m5, m5);
    const u64 M6 = f2pack(m6, m6), M7 = f2pack(m7, m7), M8 = f2pack(m8, m8);

    P2 X;
    X.x0 = f2fma(R[0], M0, f2fma(R[1], M3, f2mul(R[2], M6)));
    X.x1 = f2fma(R[0], M1, f2fma(R[1], M4, f2mul(R[2], M7)));
    X.x2 = f2fma(R[0], M2, f2fma(R[1], M5, f2mul(R[2], M8)));
    X.x3 = f2fma(R[3], M0, f2fma(R[4], M3, f2mul(R[5], M6)));
    X.x4 = f2fma(R[3], M1, f2fma(R[4], M4, f2mul(R[5], M7)));
    X.x5 = f2fma(R[3], M2, f2fma(R[4], M5, f2mul(R[5], M8)));
    X.x6 = f2fma(R[6], M0, f2fma(R[7], M3, f2mul(R[8], M6)));
    X.x7 = f2fma(R[6], M1, f2fma(R[7], M4, f2mul(R[8], M7)));
    X.x8 = f2fma(R[6], M2, f2fma(R[7], M5, f2mul(R[8], M8)));

    // ---- head: 4 unrolled det-scaled steps ----
    #pragma unroll
    for (int it = 0; it < 4; ++it) newton_scaled(X);

    // ---- tail: [fro check -> exit vote -> 2x unscaled Newton] ----
    #pragma unroll 1
    for (int ph = 0; ph < 5; ++ph) {
        u64 fro = f2mul(X.x0, X.x0);
        fro = f2fma(X.x1, X.x1, fro); fro = f2fma(X.x2, X.x2, fro);
        fro = f2fma(X.x3, X.x3, fro); fro = f2fma(X.x4, X.x4, fro);
        fro = f2fma(X.x5, X.x5, fro); fro = f2fma(X.x6, X.x6, fro);
        fro = f2fma(X.x7, X.x7, fro); fro = f2fma(X.x8, X.x8, fro);
        float fl, fh;
        f2unpack(fro, fl, fh);
        const bool ok = (fabsf(fl - 3.0f) < 2.5e-4f) && (fabsf(fh - 3.0f) < 2.5e-4f);
        if (__all_sync(0xffffffffu, ok)) break;
        newton_plain(X);
        newton_plain(X);
    }

    // ---- scatter to smem, cooperative coalesced store ----
    {
        const int olo = 2 * tid * 9, ohi = olo + 9;
        float a, b;
        f2unpack(X.x0, a, b); s[olo + 0] = a; s[ohi + 0] = b;
        f2unpack(X.x1, a, b); s[olo + 1] = a; s[ohi + 1] = b;
        f2unpack(X.x2, a, b); s[olo + 2] = a; s[ohi + 2] = b;
        f2unpack(X.x3, a, b); s[olo + 3] = a; s[ohi + 3] = b;
        f2unpack(X.x4, a, b); s[olo + 4] = a; s[ohi + 4] = b;
        f2unpack(X.x5, a, b); s[olo + 5] = a; s[ohi + 5] = b;
        f2unpack(X.x6, a, b); s[olo + 6] = a; s[ohi + 6] = b;
        f2unpack(X.x7, a, b); s[olo + 7] = a; s[ohi + 7] = b;
        f2unpack(X.x8, a, b); s[olo + 8] = a; s[ohi + 8] = b;
    }
    __syncthreads();
    {
        float* g = out + (size_t)base * 9;
        const int nv = nflt >> 2;
        const float4* s4 = reinterpret_cast<const float4*>(s);
        float4* g4 = reinterpret_cast<float4*>(g);
        for (int i = tid; i < nv; i += TPB) g4[i] = s4[i];
        for (int i = (nv << 2) + tid; i < nflt; i += TPB) g[i] = s[i];
    }

    for (int i = tid; i < nmat; i += TPB) logdet[base + i] = 0.0f;
}

__global__ void zero_tail_kernel(float* __restrict__ p, long long n)
{
    long long i = (long long)blockIdx.x * blockDim.x + threadIdx.x;
    if (i < n) p[i] = 0.0f;
}

extern "C" void kernel_launch(void* const* d_in, const int* in_sizes, int n_in,
                              void* d_out, int out_size)
{
    const float* rot = (const float*)d_in[0];
    const float* mat = (const float*)d_in[1];
    float* out = (float*)d_out;

    const int N = in_sizes[0] / 9;
    float* logdet = out + (size_t)N * 9;

    const int mats_per_block = TPB * 2;
    const int blocks = (N + mats_per_block - 1) / mats_per_block;
    polar2r_kernel<<<blocks, TPB>>>(rot, mat, out, logdet, N);

    const long long used = 10LL * N;
    if ((long long)out_size > used) {
        const long long extra = (long long)out_size - used;
        const int zb = (int)((extra + 255) / 256);
        zero_tail_kernel<<<zb, 256>>>(out + used, extra);
    }
}

// round 10
// speedup vs baseline: 1.4898x; 1.0468x over previous
#include <cuda_runtime.h>

// Polar decomposition of A = rotation[n] @ mat. 2 matrices/thread packed in
// f32x2 (FFMA2), smem-staged coalesced I/O both directions.
//  head: 4 unrolled det-scaled Newton steps (g = |det|^(-1/3) via lg2/ex2)
//  tail: unscaled Newton X <- 0.5*X + (0.5/det)*cof(X), convergence tested on
//        the det ALREADY computed inside the step (||det|-1| >= sigma_max-1,
//        so it's a strictly stronger test than the fro check, for free).

#define TPB 256
typedef unsigned long long u64;

__device__ __forceinline__ u64 f2pack(float lo, float hi) {
    u64 r; asm("mov.b64 %0, {%1, %2};" : "=l"(r) : "f"(lo), "f"(hi)); return r;
}
__device__ __forceinline__ void f2unpack(u64 v, float& lo, float& hi) {
    asm("mov.b64 {%0, %1}, %2;" : "=f"(lo), "=f"(hi) : "l"(v));
}
__device__ __forceinline__ u64 f2mul(u64 a, u64 b) {
    u64 d; asm("mul.rn.f32x2 %0, %1, %2;" : "=l"(d) : "l"(a), "l"(b)); return d;
}
__device__ __forceinline__ u64 f2fma(u64 a, u64 b, u64 c) {
    u64 d; asm("fma.rn.f32x2 %0, %1, %2, %3;" : "=l"(d) : "l"(a), "l"(b), "l"(c)); return d;
}
__device__ __forceinline__ u64 f2neg(u64 a) { return a ^ 0x8000000080000000ULL; }
__device__ __forceinline__ float lg2_fast(float x) {
    float r; asm("lg2.approx.f32 %0, %1;" : "=f"(r) : "f"(x)); return r;
}
__device__ __forceinline__ float ex2_fast(float x) {
    float r; asm("ex2.approx.f32 %0, %1;" : "=f"(r) : "f"(x)); return r;
}
__device__ __forceinline__ float rcp_fast(float x) {
    float r; asm("rcp.approx.f32 %0, %1;" : "=f"(r) : "f"(x)); return r;
}

struct P2 { u64 x0,x1,x2,x3,x4,x5,x6,x7,x8; };

// Cofactors + det with shared negations (6 negs = 12 LOP3, not 18).
__device__ __forceinline__ void cof_det(const P2& X, u64 C[9], u64& det) {
    const u64 n0 = f2neg(X.x0), n1 = f2neg(X.x1), n2 = f2neg(X.x2);
    const u64 n3 = f2neg(X.x3), n4 = f2neg(X.x4), n5 = f2neg(X.x5);
    C[0] = f2fma(X.x4, X.x8, f2mul(n5, X.x7));   // x4x8 - x5x7
    C[1] = f2fma(X.x5, X.x6, f2mul(n3, X.x8));   // x5x6 - x3x8
    C[2] = f2fma(X.x3, X.x7, f2mul(n4, X.x6));   // x3x7 - x4x6
    C[3] = f2fma(X.x2, X.x7, f2mul(n1, X.x8));   // x2x7 - x1x8
    C[4] = f2fma(X.x0, X.x8, f2mul(n2, X.x6));   // x0x8 - x2x6
    C[5] = f2fma(X.x1, X.x6, f2mul(n0, X.x7));   // x1x6 - x0x7
    C[6] = f2fma(X.x1, X.x5, f2mul(n2, X.x4));   // x1x5 - x2x4
    C[7] = f2fma(X.x2, X.x3, f2mul(n0, X.x5));   // x2x3 - x0x5
    C[8] = f2fma(X.x0, X.x4, f2mul(n1, X.x3));   // x0x4 - x1x3
    det  = f2fma(X.x0, C[0], f2fma(X.x1, C[1], f2mul(X.x2, C[2])));
}

__device__ __forceinline__ void apply(P2& X, const u64 C[9], u64 hg, u64 rr) {
    X.x0 = f2fma(rr, C[0], f2mul(hg, X.x0));
    X.x1 = f2fma(rr, C[1], f2mul(hg, X.x1));
    X.x2 = f2fma(rr, C[2], f2mul(hg, X.x2));
    X.x3 = f2fma(rr, C[3], f2mul(hg, X.x3));
    X.x4 = f2fma(rr, C[4], f2mul(hg, X.x4));
    X.x5 = f2fma(rr, C[5], f2mul(hg, X.x5));
    X.x6 = f2fma(rr, C[6], f2mul(hg, X.x6));
    X.x7 = f2fma(rr, C[7], f2mul(hg, X.x7));
    X.x8 = f2fma(rr, C[8], f2mul(hg, X.x8));
}

// Det-scaled Newton (head). 0.5/(g*det) = 0.5*g^2*sign(det) exactly.
__device__ __forceinline__ void newton_scaled(P2& X) {
    u64 C[9], det;
    cof_det(X, C, det);
    float dl, dh;
    f2unpack(det, dl, dh);
    const float gl = ex2_fast(-0.33333333f * lg2_fast(fmaxf(fabsf(dl), 1e-36f)));
    const float gh = ex2_fast(-0.33333333f * lg2_fast(fmaxf(fabsf(dh), 1e-36f)));
    const float rl = copysignf(0.5f * gl * gl, dl);
    const float rh = copysignf(0.5f * gh * gh, dh);
    apply(X, C, f2pack(0.5f * gl, 0.5f * gh), f2pack(rl, rh));
}

// Unscaled Newton (tail). Returns whether det(X_input) was converged —
// ||det|-1| >= sigma_max(X_in)-1 when all sigma >= 1, so this is a
// strictly stronger convergence certificate than the fro check, for free.
__device__ __forceinline__ bool newton_plain_check(P2& X) {
    u64 C[9], det;
    cof_det(X, C, det);
    float dl, dh;
    f2unpack(det, dl, dh);
    const float rl = 0.5f * rcp_fast(dl);
    const float rh = 0.5f * rcp_fast(dh);
    apply(X, C, 0x3F0000003F000000ULL /*(0.5f,0.5f)*/, f2pack(rl, rh));
    return (fabsf(fabsf(dl) - 1.0f) < 2.5e-4f) &&
           (fabsf(fabsf(dh) - 1.0f) < 2.5e-4f);
}

__global__ void __launch_bounds__(TPB)
polar2e_kernel(const float* __restrict__ rot,
               const float* __restrict__ mat,
               float* __restrict__ out,
               float* __restrict__ logdet,
               int N)
{
    __shared__ float s[TPB * 18];
    const int tid  = threadIdx.x;
    const int base = blockIdx.x * (TPB * 2);
    const int nmat = min(TPB * 2, N - base);
    const int nflt = nmat * 9;

    // ---- cooperative coalesced load: global -> smem ----
    {
        const float* g = rot + (size_t)base * 9;
        const int nv = nflt >> 2;
        const float4* g4 = reinterpret_cast<const float4*>(g);
        float4* s4 = reinterpret_cast<float4*>(s);
        for (int i = tid; i < nv; i += TPB) s4[i] = g4[i];
        for (int i = (nv << 2) + tid; i < nflt; i += TPB) s[i] = g[i];
    }

    const float m0 = __ldg(mat + 0), m1 = __ldg(mat + 1), m2 = __ldg(mat + 2);
    const float m3 = __ldg(mat + 3), m4 = __ldg(mat + 4), m5 = __ldg(mat + 5);
    const float m6 = __ldg(mat + 6), m7 = __ldg(mat + 7), m8 = __ldg(mat + 8);
    __syncthreads();

    const bool vlo = (base + 2 * tid)     < N;
    const bool vhi = (base + 2 * tid + 1) < N;

    u64 R[9];
    {
        const int olo = 2 * tid * 9, ohi = olo + 9;
        #pragma unroll
        for (int k = 0; k < 9; ++k) {
            const float idv = (k == 0 || k == 4 || k == 8) ? 1.0f : 0.0f;
            const float a = vlo ? s[olo + k] : idv;
            const float b = vhi ? s[ohi + k] : idv;
            R[k] = f2pack(a, b);
        }
    }
    __syncthreads();   // smem reused for store staging

    const u64 M0 = f2pack(m0, m0), M1 = f2pack(m1, m1), M2 = f2pack(m2, m2);
    const u64 M3 = f2pack(m3, m3), M4 = f2pack(m4, m4), M5 = f2pack(m5, m5);
    const u64 M6 = f2pack(m6, m6), M7 = f2pack(m7, m7), M8 = f2pack(m8, m8);

    P2 X;
    X.x0 = f2fma(R[0], M0, f2fma(R[1], M3, f2mul(R[2], M6)));
    X.x1 = f2fma(R[0], M1, f2fma(R[1], M4, f2mul(R[2], M7)));
    X.x2 = f2fma(R[0], M2, f2fma(R[1], M5, f2mul(R[2], M8)));
    X.x3 = f2fma(R[3], M0, f2fma(R[4], M3, f2mul(R[5], M6)));
    X.x4 = f2fma(R[3], M1, f2fma(R[4], M4, f2mul(R[5], M7)));
    X.x5 = f2fma(R[3], M2, f2fma(R[4], M5, f2mul(R[5], M8)));
    X.x6 = f2fma(R[6], M0, f2fma(R[7], M3, f2mul(R[8], M6)));
    X.x7 = f2fma(R[6], M1, f2fma(R[7], M4, f2mul(R[8], M7)));
    X.x8 = f2fma(R[6], M2, f2fma(R[7], M5, f2mul(R[8], M8)));

    // ---- head: 4 unrolled det-scaled steps, no checks ----
    #pragma unroll
    for (int it = 0; it < 4; ++it) newton_scaled(X);

    // ---- tail: plain Newton, test-after-step on the step's own det ----
    #pragma unroll 1
    for (int it = 0; it < 8; ++it) {
        const bool ok = newton_plain_check(X);
        if (__all_sync(0xffffffffu, ok)) break;
    }

    // ---- scatter to smem, cooperative coalesced store ----
    {
        const int olo = 2 * tid * 9, ohi = olo + 9;
        float a, b;
        f2unpack(X.x0, a, b); s[olo + 0] = a; s[ohi + 0] = b;
        f2unpack(X.x1, a, b); s[olo + 1] = a; s[ohi + 1] = b;
        f2unpack(X.x2, a, b); s[olo + 2] = a; s[ohi + 2] = b;
        f2unpack(X.x3, a, b); s[olo + 3] = a; s[ohi + 3] = b;
        f2unpack(X.x4, a, b); s[olo + 4] = a; s[ohi + 4] = b;
        f2unpack(X.x5, a, b); s[olo + 5] = a; s[ohi + 5] = b;
        f2unpack(X.x6, a, b); s[olo + 6] = a; s[ohi + 6] = b;
        f2unpack(X.x7, a, b); s[olo + 7] = a; s[ohi + 7] = b;
        f2unpack(X.x8, a, b); s[olo + 8] = a; s[ohi + 8] = b;
    }
    __syncthreads();
    {
        float* g = out + (size_t)base * 9;
        const int nv = nflt >> 2;
        const float4* s4 = reinterpret_cast<const float4*>(s);
        float4* g4 = reinterpret_cast<float4*>(g);
        for (int i = tid; i < nv; i += TPB) g4[i] = s4[i];
        for (int i = (nv << 2) + tid; i < nflt; i += TPB) g[i] = s[i];
    }

    for (int i = tid; i < nmat; i += TPB) logdet[base + i] = 0.0f;
}

__global__ void zero_tail_kernel(float* __restrict__ p, long long n)
{
    long long i = (long long)blockIdx.x * blockDim.x + threadIdx.x;
    if (i < n) p[i] = 0.0f;
}

extern "C" void kernel_launch(void* const* d_in, const int* in_sizes, int n_in,
                              void* d_out, int out_size)
{
    const float* rot = (const float*)d_in[0];
    const float* mat = (const float*)d_in[1];
    float* out = (float*)d_out;

    const int N = in_sizes[0] / 9;
    float* logdet = out + (size_t)N * 9;

    const int mats_per_block = TPB * 2;
    const int blocks = (N + mats_per_block - 1) / mats_per_block;
    polar2e_kernel<<<blocks, TPB>>>(rot, mat, out, logdet, N);

    const long long used = 10LL * N;
    if ((long long)out_size > used) {
        const long long extra = (long long)out_size - used;
        const int zb = (int)((extra + 255) / 256);
        zero_tail_kernel<<<zb, 256>>>(out + used, extra);
    }
}

// round 11
// speedup vs baseline: 1.4923x; 1.0017x over previous
#include <cuda_runtime.h>

// Polar decomposition of A = rotation[n] @ mat. 2 matrices/thread packed in
// f32x2 (FFMA2), smem-staged coalesced I/O. Fully MUFU-free:
// every step is det-scaled Newton  X <- 0.5*g*X + 0.5*g^2*sign(det)*cof(X),
// g = |det|^(-1/3) via bit-trick + TWO FMA Newton polishes (~1e-6 accurate).
// Tail exit: |det(X_in)| within 1e-2 of 1 AFTER performing the step —
// quadratic convergence turns that into ~5e-5 element error, and det is
// computed inside the step anyway, so the test is free.

#define TPB 256
typedef unsigned long long u64;

__device__ __forceinline__ u64 f2pack(float lo, float hi) {
    u64 r; asm("mov.b64 %0, {%1, %2};" : "=l"(r) : "f"(lo), "f"(hi)); return r;
}
__device__ __forceinline__ void f2unpack(u64 v, float& lo, float& hi) {
    asm("mov.b64 {%0, %1}, %2;" : "=f"(lo), "=f"(hi) : "l"(v));
}
__device__ __forceinline__ u64 f2mul(u64 a, u64 b) {
    u64 d; asm("mul.rn.f32x2 %0, %1, %2;" : "=l"(d) : "l"(a), "l"(b)); return d;
}
__device__ __forceinline__ u64 f2fma(u64 a, u64 b, u64 c) {
    u64 d; asm("fma.rn.f32x2 %0, %1, %2, %3;" : "=l"(d) : "l"(a), "l"(b), "l"(c)); return d;
}
__device__ __forceinline__ u64 f2neg(u64 a) { return a ^ 0x8000000080000000ULL; }

// |x|^(-1/3): bit trick + 2 Newton polishes -> ~1e-6 rel error, zero MUFU.
__device__ __forceinline__ float invcbrt2(float x) {
    int i = __float_as_int(x);
    i = 0x54A2FA8C - i / 3;
    float y = __int_as_float(i);
    float y3 = y * y * y;
    y = y * 0.33333333f * fmaf(-x, y3, 4.0f);
    y3 = y * y * y;
    y = y * 0.33333333f * fmaf(-x, y3, 4.0f);
    return y;
}

struct P2 { u64 x0,x1,x2,x3,x4,x5,x6,x7,x8; };

// Cofactors + det, 6 shared negations.
__device__ __forceinline__ void cof_det(const P2& X, u64 C[9], u64& det) {
    const u64 n0 = f2neg(X.x0), n1 = f2neg(X.x1), n2 = f2neg(X.x2);
    const u64 n3 = f2neg(X.x3), n4 = f2neg(X.x4), n5 = f2neg(X.x5);
    C[0] = f2fma(X.x4, X.x8, f2mul(n5, X.x7));
    C[1] = f2fma(X.x5, X.x6, f2mul(n3, X.x8));
    C[2] = f2fma(X.x3, X.x7, f2mul(n4, X.x6));
    C[3] = f2fma(X.x2, X.x7, f2mul(n1, X.x8));
    C[4] = f2fma(X.x0, X.x8, f2mul(n2, X.x6));
    C[5] = f2fma(X.x1, X.x6, f2mul(n0, X.x7));
    C[6] = f2fma(X.x1, X.x5, f2mul(n2, X.x4));
    C[7] = f2fma(X.x2, X.x3, f2mul(n0, X.x5));
    C[8] = f2fma(X.x0, X.x4, f2mul(n1, X.x3));
    det  = f2fma(X.x0, C[0], f2fma(X.x1, C[1], f2mul(X.x2, C[2])));
}

__device__ __forceinline__ void apply(P2& X, const u64 C[9], u64 hg, u64 rr) {
    X.x0 = f2fma(rr, C[0], f2mul(hg, X.x0));
    X.x1 = f2fma(rr, C[1], f2mul(hg, X.x1));
    X.x2 = f2fma(rr, C[2], f2mul(hg, X.x2));
    X.x3 = f2fma(rr, C[3], f2mul(hg, X.x3));
    X.x4 = f2fma(rr, C[4], f2mul(hg, X.x4));
    X.x5 = f2fma(rr, C[5], f2mul(hg, X.x5));
    X.x6 = f2fma(rr, C[6], f2mul(hg, X.x6));
    X.x7 = f2fma(rr, C[7], f2mul(hg, X.x7));
    X.x8 = f2fma(rr, C[8], f2mul(hg, X.x8));
}

// One det-scaled Newton step, MUFU-free. Returns true iff |det(X_in)| was
// already within 1e-2 of 1 — valid exit test because every scaled step
// outputs all sigma >= 1 (so |det|-1 >= sigma_max-1), and the step just
// performed polishes the error quadratically (1e-2 -> ~5e-5).
__device__ __forceinline__ bool step_check(P2& X) {
    u64 C[9], det;
    cof_det(X, C, det);
    float dl, dh;
    f2unpack(det, dl, dh);
    const float al = fmaxf(fabsf(dl), 1e-30f);
    const float ah = fmaxf(fabsf(dh), 1e-30f);
    const float gl = invcbrt2(al);
    const float gh = invcbrt2(ah);
    const float rl = copysignf(0.5f * gl * gl, dl);   // 0.5/(g*det) exactly
    const float rh = copysignf(0.5f * gh * gh, dh);
    apply(X, C, f2pack(0.5f * gl, 0.5f * gh), f2pack(rl, rh));
    return (fabsf(al - 1.0f) < 1e-2f) && (fabsf(ah - 1.0f) < 1e-2f);
}

__global__ void __launch_bounds__(TPB)
polar2m_kernel(const float* __restrict__ rot,
               const float* __restrict__ mat,
               float* __restrict__ out,
               float* __restrict__ logdet,
               int N)
{
    __shared__ float s[TPB * 18];
    const int tid  = threadIdx.x;
    const int base = blockIdx.x * (TPB * 2);
    const int nmat = min(TPB * 2, N - base);
    const int nflt = nmat * 9;

    // ---- cooperative coalesced load: global -> smem ----
    {
        const float* g = rot + (size_t)base * 9;
        const int nv = nflt >> 2;
        const float4* g4 = reinterpret_cast<const float4*>(g);
        float4* s4 = reinterpret_cast<float4*>(s);
        for (int i = tid; i < nv; i += TPB) s4[i] = g4[i];
        for (int i = (nv << 2) + tid; i < nflt; i += TPB) s[i] = g[i];
    }

    const float m0 = __ldg(mat + 0), m1 = __ldg(mat + 1), m2 = __ldg(mat + 2);
    const float m3 = __ldg(mat + 3), m4 = __ldg(mat + 4), m5 = __ldg(mat + 5);
    const float m6 = __ldg(mat + 6), m7 = __ldg(mat + 7), m8 = __ldg(mat + 8);
    __syncthreads();

    const bool vlo = (base + 2 * tid)     < N;
    const bool vhi = (base + 2 * tid + 1) < N;

    u64 R[9];
    {
        const int olo = 2 * tid * 9, ohi = olo + 9;
        #pragma unroll
        for (int k = 0; k < 9; ++k) {
            const float idv = (k == 0 || k == 4 || k == 8) ? 1.0f : 0.0f;
            const float a = vlo ? s[olo + k] : idv;
            const float b = vhi ? s[ohi + k] : idv;
            R[k] = f2pack(a, b);
        }
    }
    __syncthreads();   // smem reused for store staging

    const u64 M0 = f2pack(m0, m0), M1 = f2pack(m1, m1), M2 = f2pack(m2, m2);
    const u64 M3 = f2pack(m3, m3), M4 = f2pack(m4, m4), M5 = f2pack(m5, m5);
    const u64 M6 = f2pack(m6, m6), M7 = f2pack(m7, m7), M8 = f2pack(m8, m8);

    P2 X;
    X.x0 = f2fma(R[0], M0, f2fma(R[1], M3, f2mul(R[2], M6)));
    X.x1 = f2fma(R[0], M1, f2fma(R[1], M4, f2mul(R[2], M7)));
    X.x2 = f2fma(R[0], M2, f2fma(R[1], M5, f2mul(R[2], M8)));
    X.x3 = f2fma(R[3], M0, f2fma(R[4], M3, f2mul(R[5], M6)));
    X.x4 = f2fma(R[3], M1, f2fma(R[4], M4, f2mul(R[5], M7)));
    X.x5 = f2fma(R[3], M2, f2fma(R[4], M5, f2mul(R[5], M8)));
    X.x6 = f2fma(R[6], M0, f2fma(R[7], M3, f2mul(R[8], M6)));
    X.x7 = f2fma(R[6], M1, f2fma(R[7], M4, f2mul(R[8], M7)));
    X.x8 = f2fma(R[6], M2, f2fma(R[7], M5, f2mul(R[8], M8)));

    // ---- head: 3 unrolled steps, ignore the test ----
    #pragma unroll
    for (int it = 0; it < 3; ++it) (void)step_check(X);

    // ---- tail: test-after-step with warp-uniform exit ----
    #pragma unroll 1
    for (int it = 0; it < 9; ++it) {
        const bool ok = step_check(X);
        if (__all_sync(0xffffffffu, ok)) break;
    }

    // ---- scatter to smem, cooperative coalesced store ----
    {
        const int olo = 2 * tid * 9, ohi = olo + 9;
        float a, b;
        f2unpack(X.x0, a, b); s[olo + 0] = a; s[ohi + 0] = b;
        f2unpack(X.x1, a, b); s[olo + 1] = a; s[ohi + 1] = b;
        f2unpack(X.x2, a, b); s[olo + 2] = a; s[ohi + 2] = b;
        f2unpack(X.x3, a, b); s[olo + 3] = a; s[ohi + 3] = b;
        f2unpack(X.x4, a, b); s[olo + 4] = a; s[ohi + 4] = b;
        f2unpack(X.x5, a, b); s[olo + 5] = a; s[ohi + 5] = b;
        f2unpack(X.x6, a, b); s[olo + 6] = a; s[ohi + 6] = b;
        f2unpack(X.x7, a, b); s[olo + 7] = a; s[ohi + 7] = b;
        f2unpack(X.x8, a, b); s[olo + 8] = a; s[ohi + 8] = b;
    }
    __syncthreads();
    {
        float* g = out + (size_t)base * 9;
        const int nv = nflt >> 2;
        const float4* s4 = reinterpret_cast<const float4*>(s);
        float4* g4 = reinterpret_cast<float4*>(g);
        for (int i = tid; i < nv; i += TPB) g4[i] = s4[i];
        for (int i = (nv << 2) + tid; i < nflt; i += TPB) g[i] = s[i];
    }

    for (int i = tid; i < nmat; i += TPB) logdet[base + i] = 0.0f;
}

__global__ void zero_tail_kernel(float* __restrict__ p, long long n)
{
    long long i = (long long)blockIdx.x * blockDim.x + threadIdx.x;
    if (i < n) p[i] = 0.0f;
}

extern "C" void kernel_launch(void* const* d_in, const int* in_sizes, int n_in,
                              void* d_out, int out_size)
{
    const float* rot = (const float*)d_in[0];
    const float* mat = (const float*)d_in[1];
    float* out = (float*)d_out;

    const int N = in_sizes[0] / 9;
    float* logdet = out + (size_t)N * 9;

    const int mats_per_block = TPB * 2;
    const int blocks = (N + mats_per_block - 1) / mats_per_block;
    polar2m_kernel<<<blocks, TPB>>>(rot, mat, out, logdet, N);

    const long long used = 10LL * N;
    if ((long long)out_size > used) {
        const long long extra = (long long)out_size - used;
        const int zb = (int)((extra + 255) / 256);
        zero_tail_kernel<<<zb, 256>>>(out + used, extra);
    }
}

// round 12
// speedup vs baseline: 1.5755x; 1.0558x over previous
#include <cuda_runtime.h>

// Polar decomposition of A = rotation[n] @ mat. ONE WARP PER CTA (TPB=32):
// no __syncthreads anywhere, so each warp/CTA retires as soon as its own 64
// matrices converge (eliminates the cross-warp barrier straggler wait that
// pinned issue% at ~63 in all TPB=256 variants).
// Math: 2 matrices/thread packed f32x2, MUFU-free det-scaled Newton
//   X <- 0.5*g*X + 0.5*g^2*sign(det)*cof(X),  g = |det|^(-1/3) (bit trick,
//   2 FMA polishes), free |det|-1 test-after-step, head 3 + voted tail.

#define TPB 32
typedef unsigned long long u64;

__device__ __forceinline__ u64 f2pack(float lo, float hi) {
    u64 r; asm("mov.b64 %0, {%1, %2};" : "=l"(r) : "f"(lo), "f"(hi)); return r;
}
__device__ __forceinline__ void f2unpack(u64 v, float& lo, float& hi) {
    asm("mov.b64 {%0, %1}, %2;" : "=f"(lo), "=f"(hi) : "l"(v));
}
__device__ __forceinline__ u64 f2mul(u64 a, u64 b) {
    u64 d; asm("mul.rn.f32x2 %0, %1, %2;" : "=l"(d) : "l"(a), "l"(b)); return d;
}
__device__ __forceinline__ u64 f2fma(u64 a, u64 b, u64 c) {
    u64 d; asm("fma.rn.f32x2 %0, %1, %2, %3;" : "=l"(d) : "l"(a), "l"(b), "l"(c)); return d;
}
__device__ __forceinline__ u64 f2neg(u64 a) { return a ^ 0x8000000080000000ULL; }

// |x|^(-1/3): bit trick + 2 FMA Newton polishes (~1e-6), zero MUFU.
__device__ __forceinline__ float invcbrt2(float x) {
    int i = __float_as_int(x);
    i = 0x54A2FA8C - i / 3;
    float y = __int_as_float(i);
    float y3 = y * y * y;
    y = y * 0.33333333f * fmaf(-x, y3, 4.0f);
    y3 = y * y * y;
    y = y * 0.33333333f * fmaf(-x, y3, 4.0f);
    return y;
}

struct P2 { u64 x0,x1,x2,x3,x4,x5,x6,x7,x8; };

__device__ __forceinline__ void cof_det(const P2& X, u64 C[9], u64& det) {
    const u64 n0 = f2neg(X.x0), n1 = f2neg(X.x1), n2 = f2neg(X.x2);
    const u64 n3 = f2neg(X.x3), n4 = f2neg(X.x4), n5 = f2neg(X.x5);
    C[0] = f2fma(X.x4, X.x8, f2mul(n5, X.x7));
    C[1] = f2fma(X.x5, X.x6, f2mul(n3, X.x8));
    C[2] = f2fma(X.x3, X.x7, f2mul(n4, X.x6));
    C[3] = f2fma(X.x2, X.x7, f2mul(n1, X.x8));
    C[4] = f2fma(X.x0, X.x8, f2mul(n2, X.x6));
    C[5] = f2fma(X.x1, X.x6, f2mul(n0, X.x7));
    C[6] = f2fma(X.x1, X.x5, f2mul(n2, X.x4));
    C[7] = f2fma(X.x2, X.x3, f2mul(n0, X.x5));
    C[8] = f2fma(X.x0, X.x4, f2mul(n1, X.x3));
    det  = f2fma(X.x0, C[0], f2fma(X.x1, C[1], f2mul(X.x2, C[2])));
}

__device__ __forceinline__ void apply(P2& X, const u64 C[9], u64 hg, u64 rr) {
    X.x0 = f2fma(rr, C[0], f2mul(hg, X.x0));
    X.x1 = f2fma(rr, C[1], f2mul(hg, X.x1));
    X.x2 = f2fma(rr, C[2], f2mul(hg, X.x2));
    X.x3 = f2fma(rr, C[3], f2mul(hg, X.x3));
    X.x4 = f2fma(rr, C[4], f2mul(hg, X.x4));
    X.x5 = f2fma(rr, C[5], f2mul(hg, X.x5));
    X.x6 = f2fma(rr, C[6], f2mul(hg, X.x6));
    X.x7 = f2fma(rr, C[7], f2mul(hg, X.x7));
    X.x8 = f2fma(rr, C[8], f2mul(hg, X.x8));
}

// One det-scaled step; true iff |det(X_in)| within 1e-2 of 1 (the step just
// performed polishes quadratically: 1e-2 -> ~5e-5 element error).
__device__ __forceinline__ bool step_check(P2& X) {
    u64 C[9], det;
    cof_det(X, C, det);
    float dl, dh;
    f2unpack(det, dl, dh);
    const float al = fmaxf(fabsf(dl), 1e-30f);
    const float ah = fmaxf(fabsf(dh), 1e-30f);
    const float gl = invcbrt2(al);
    const float gh = invcbrt2(ah);
    const float rl = copysignf(0.5f * gl * gl, dl);
    const float rh = copysignf(0.5f * gh * gh, dh);
    apply(X, C, f2pack(0.5f * gl, 0.5f * gh), f2pack(rl, rh));
    return (fabsf(al - 1.0f) < 1e-2f) && (fabsf(ah - 1.0f) < 1e-2f);
}

__global__ void __launch_bounds__(TPB)
polar_w_kernel(const float* __restrict__ rot,
               const float* __restrict__ mat,
               float* __restrict__ out,
               float* __restrict__ logdet,
               int N)
{
    __shared__ float s[TPB * 18];                 // 2.25 KB, one warp's tile
    const int tid  = threadIdx.x;
    const int base = blockIdx.x * (TPB * 2);      // 64 matrices per warp/CTA
    const int nmat = min(TPB * 2, N - base);
    const int nflt = nmat * 9;

    // ---- cooperative coalesced load: global -> smem (within one warp) ----
    {
        const float* g = rot + (size_t)base * 9;
        const int nv = nflt >> 2;
        const float4* g4 = reinterpret_cast<const float4*>(g);
        float4* s4 = reinterpret_cast<float4*>(s);
        for (int i = tid; i < nv; i += TPB) s4[i] = g4[i];
        for (int i = (nv << 2) + tid; i < nflt; i += TPB) s[i] = g[i];
    }

    const float m0 = __ldg(mat + 0), m1 = __ldg(mat + 1), m2 = __ldg(mat + 2);
    const float m3 = __ldg(mat + 3), m4 = __ldg(mat + 4), m5 = __ldg(mat + 5);
    const float m6 = __ldg(mat + 6), m7 = __ldg(mat + 7), m8 = __ldg(mat + 8);
    __syncwarp();

    const bool vlo = (base + 2 * tid)     < N;
    const bool vhi = (base + 2 * tid + 1) < N;

    u64 R[9];
    {
        const int olo = 2 * tid * 9, ohi = olo + 9;
        #pragma unroll
        for (int k = 0; k < 9; ++k) {
            const float idv = (k == 0 || k == 4 || k == 8) ? 1.0f : 0.0f;
            const float a = vlo ? s[olo + k] : idv;
            const float b = vhi ? s[ohi + k] : idv;
            R[k] = f2pack(a, b);
        }
    }
    __syncwarp();

    const u64 M0 = f2pack(m0, m0), M1 = f2pack(m1, m1), M2 = f2pack(m2, m2);
    const u64 M3 = f2pack(m3, m3), M4 = f2pack(m4, m4), M5 = f2pack(m5, m5);
    const u64 M6 = f2pack(m6, m6), M7 = f2pack(m7, m7), M8 = f2pack(m8, m8);

    P2 X;
    X.x0 = f2fma(R[0], M0, f2fma(R[1], M3, f2mul(R[2], M6)));
    X.x1 = f2fma(R[0], M1, f2fma(R[1], M4, f2mul(R[2], M7)));
    X.x2 = f2fma(R[0], M2, f2fma(R[1], M5, f2mul(R[2], M8)));
    X.x3 = f2fma(R[3], M0, f2fma(R[4], M3, f2mul(R[5], M6)));
    X.x4 = f2fma(R[3], M1, f2fma(R[4], M4, f2mul(R[5], M7)));
    X.x5 = f2fma(R[3], M2, f2fma(R[4], M5, f2mul(R[5], M8)));
    X.x6 = f2fma(R[6], M0, f2fma(R[7], M3, f2mul(R[8], M6)));
    X.x7 = f2fma(R[6], M1, f2fma(R[7], M4, f2mul(R[8], M7)));
    X.x8 = f2fma(R[6], M2, f2fma(R[7], M5, f2mul(R[8], M8)));

    // ---- head: 3 unrolled steps ----
    #pragma unroll
    for (int it = 0; it < 3; ++it) (void)step_check(X);

    // ---- tail: test-after-step, warp-uniform exit -> CTA retires early ----
    #pragma unroll 1
    for (int it = 0; it < 9; ++it) {
        const bool ok = step_check(X);
        if (__all_sync(0xffffffffu, ok)) break;
    }

    // ---- scatter to smem, cooperative coalesced store (same warp) ----
    {
        const int olo = 2 * tid * 9, ohi = olo + 9;
        float a, b;
        f2unpack(X.x0, a, b); s[olo + 0] = a; s[ohi + 0] = b;
        f2unpack(X.x1, a, b); s[olo + 1] = a; s[ohi + 1] = b;
        f2unpack(X.x2, a, b); s[olo + 2] = a; s[ohi + 2] = b;
        f2unpack(X.x3, a, b); s[olo + 3] = a; s[ohi + 3] = b;
        f2unpack(X.x4, a, b); s[olo + 4] = a; s[ohi + 4] = b;
        f2unpack(X.x5, a, b); s[olo + 5] = a; s[ohi + 5] = b;
        f2unpack(X.x6, a, b); s[olo + 6] = a; s[ohi + 6] = b;
        f2unpack(X.x7, a, b); s[olo + 7] = a; s[ohi + 7] = b;
        f2unpack(X.x8, a, b); s[olo + 8] = a; s[ohi + 8] = b;
    }
    __syncwarp();
    {
        float* g = out + (size_t)base * 9;
        const int nv = nflt >> 2;
        const float4* s4 = reinterpret_cast<const float4*>(s);
        float4* g4 = reinterpret_cast<float4*>(g);
        for (int i = tid; i < nv; i += TPB) g4[i] = s4[i];
        for (int i = (nv << 2) + tid; i < nflt; i += TPB) g[i] = s[i];
    }

    for (int i = tid; i < nmat; i += TPB) logdet[base + i] = 0.0f;
}

__global__ void zero_tail_kernel(float* __restrict__ p, long long n)
{
    long long i = (long long)blockIdx.x * blockDim.x + threadIdx.x;
    if (i < n) p[i] = 0.0f;
}

extern "C" void kernel_launch(void* const* d_in, const int* in_sizes, int n_in,
                              void* d_out, int out_size)
{
    const float* rot = (const float*)d_in[0];
    const float* mat = (const float*)d_in[1];
    float* out = (float*)d_out;

    const int N = in_sizes[0] / 9;
    float* logdet = out + (size_t)N * 9;

    const int mats_per_block = TPB * 2;
    const int blocks = (N + mats_per_block - 1) / mats_per_block;
    polar_w_kernel<<<blocks, TPB>>>(rot, mat, out, logdet, N);

    const long long used = 10LL * N;
    if ((long long)out_size > used) {
        const long long extra = (long long)out_size - used;
        const int zb = (int)((extra + 255) / 256);
        zero_tail_kernel<<<zb, 256>>>(out + used, extra);
    }
}

// round 13
// speedup vs baseline: 1.6252x; 1.0315x over previous
#include <cuda_runtime.h>

// Polar decomposition of A = rotation[n] @ mat. One warp per CTA (TPB=32,
// no __syncthreads -> per-warp early retirement; R12-validated shell).
// 2 matrices/thread packed f32x2.
//  head: 3 det-scaled Newton steps, g=|det|^(-1/3) via bit trick + ONE FMA
//        polish (g is pure preconditioning here - accuracy irrelevant).
//  tail: PLAIN Newton X <- 0.5*X + (0.5/det)*cof(X) via rcp.approx - its
//        fixpoint is exactly orthogonal, so it erases any head scale error.
//        Free exit test: |det(X_in)|-1 within 1e-2, tested AFTER the step
//        (quadratic convergence -> ~2.5e-5 final element error).

#define TPB 32
typedef unsigned long long u64;

__device__ __forceinline__ u64 f2pack(float lo, float hi) {
    u64 r; asm("mov.b64 %0, {%1, %2};" : "=l"(r) : "f"(lo), "f"(hi)); return r;
}
__device__ __forceinline__ void f2unpack(u64 v, float& lo, float& hi) {
    asm("mov.b64 {%0, %1}, %2;" : "=f"(lo), "=f"(hi) : "l"(v));
}
__device__ __forceinline__ u64 f2mul(u64 a, u64 b) {
    u64 d; asm("mul.rn.f32x2 %0, %1, %2;" : "=l"(d) : "l"(a), "l"(b)); return d;
}
__device__ __forceinline__ u64 f2fma(u64 a, u64 b, u64 c) {
    u64 d; asm("fma.rn.f32x2 %0, %1, %2, %3;" : "=l"(d) : "l"(a), "l"(b), "l"(c)); return d;
}
__device__ __forceinline__ u64 f2neg(u64 a) { return a ^ 0x8000000080000000ULL; }
__device__ __forceinline__ float rcp_fast(float x) {
    float r; asm("rcp.approx.f32 %0, %1;" : "=f"(r) : "f"(x)); return r;
}

// |x|^(-1/3): bit trick + 1 FMA polish (~2e-3 - plenty for preconditioning).
__device__ __forceinline__ float invcbrt1(float x) {
    int i = __float_as_int(x);
    i = 0x54A2FA8C - i / 3;
    float y = __int_as_float(i);
    const float y3 = y * y * y;
    return y * 0.33333333f * fmaf(-x, y3, 4.0f);
}

struct P2 { u64 x0,x1,x2,x3,x4,x5,x6,x7,x8; };

__device__ __forceinline__ void cof_det(const P2& X, u64 C[9], u64& det) {
    const u64 n0 = f2neg(X.x0), n1 = f2neg(X.x1), n2 = f2neg(X.x2);
    const u64 n3 = f2neg(X.x3), n4 = f2neg(X.x4), n5 = f2neg(X.x5);
    C[0] = f2fma(X.x4, X.x8, f2mul(n5, X.x7));
    C[1] = f2fma(X.x5, X.x6, f2mul(n3, X.x8));
    C[2] = f2fma(X.x3, X.x7, f2mul(n4, X.x6));
    C[3] = f2fma(X.x2, X.x7, f2mul(n1, X.x8));
    C[4] = f2fma(X.x0, X.x8, f2mul(n2, X.x6));
    C[5] = f2fma(X.x1, X.x6, f2mul(n0, X.x7));
    C[6] = f2fma(X.x1, X.x5, f2mul(n2, X.x4));
    C[7] = f2fma(X.x2, X.x3, f2mul(n0, X.x5));
    C[8] = f2fma(X.x0, X.x4, f2mul(n1, X.x3));
    det  = f2fma(X.x0, C[0], f2fma(X.x1, C[1], f2mul(X.x2, C[2])));
}

__device__ __forceinline__ void apply(P2& X, const u64 C[9], u64 hg, u64 rr) {
    X.x0 = f2fma(rr, C[0], f2mul(hg, X.x0));
    X.x1 = f2fma(rr, C[1], f2mul(hg, X.x1));
    X.x2 = f2fma(rr, C[2], f2mul(hg, X.x2));
    X.x3 = f2fma(rr, C[3], f2mul(hg, X.x3));
    X.x4 = f2fma(rr, C[4], f2mul(hg, X.x4));
    X.x5 = f2fma(rr, C[5], f2mul(hg, X.x5));
    X.x6 = f2fma(rr, C[6], f2mul(hg, X.x6));
    X.x7 = f2fma(rr, C[7], f2mul(hg, X.x7));
    X.x8 = f2fma(rr, C[8], f2mul(hg, X.x8));
}

// Head step: det-scaled Newton with cheap 1-polish g.
__device__ __forceinline__ void step_scaled(P2& X) {
    u64 C[9], det;
    cof_det(X, C, det);
    float dl, dh;
    f2unpack(det, dl, dh);
    const float gl = invcbrt1(fmaxf(fabsf(dl), 1e-30f));
    const float gh = invcbrt1(fmaxf(fabsf(dh), 1e-30f));
    const float rl = copysignf(0.5f * gl * gl, dl);
    const float rh = copysignf(0.5f * gh * gh, dh);
    apply(X, C, f2pack(0.5f * gl, 0.5f * gh), f2pack(rl, rh));
}

// Tail step: plain Newton (exact orthogonal fixpoint). Returns true iff
// |det(X_in)| was within 1e-2 of 1 - the step just performed polishes
// quadratically, so accepted outputs have ~2.5e-5 element error.
__device__ __forceinline__ bool step_plain(P2& X) {
    u64 C[9], det;
    cof_det(X, C, det);
    float dl, dh;
    f2unpack(det, dl, dh);
    const float rl = 0.5f * rcp_fast(dl);
    const float rh = 0.5f * rcp_fast(dh);
    apply(X, C, 0x3F0000003F000000ULL /*(0.5f,0.5f)*/, f2pack(rl, rh));
    return (fabsf(fabsf(dl) - 1.0f) < 1e-2f) &&
           (fabsf(fabsf(dh) - 1.0f) < 1e-2f);
}

__global__ void __launch_bounds__(TPB)
polar_w2_kernel(const float* __restrict__ rot,
                const float* __restrict__ mat,
                float* __restrict__ out,
                float* __restrict__ logdet,
                int N)
{
    __shared__ float s[TPB * 18];
    const int tid  = threadIdx.x;
    const int base = blockIdx.x * (TPB * 2);
    const int nmat = min(TPB * 2, N - base);
    const int nflt = nmat * 9;

    // ---- cooperative coalesced load: global -> smem (one warp) ----
    {
        const float* g = rot + (size_t)base * 9;
        const int nv = nflt >> 2;
        const float4* g4 = reinterpret_cast<const float4*>(g);
        float4* s4 = reinterpret_cast<float4*>(s);
        for (int i = tid; i < nv; i += TPB) s4[i] = g4[i];
        for (int i = (nv << 2) + tid; i < nflt; i += TPB) s[i] = g[i];
    }

    const float m0 = __ldg(mat + 0), m1 = __ldg(mat + 1), m2 = __ldg(mat + 2);
    const float m3 = __ldg(mat + 3), m4 = __ldg(mat + 4), m5 = __ldg(mat + 5);
    const float m6 = __ldg(mat + 6), m7 = __ldg(mat + 7), m8 = __ldg(mat + 8);
    __syncwarp();

    const bool vlo = (base + 2 * tid)     < N;
    const bool vhi = (base + 2 * tid + 1) < N;

    u64 R[9];
    {
        const int olo = 2 * tid * 9, ohi = olo + 9;
        #pragma unroll
        for (int k = 0; k < 9; ++k) {
            const float idv = (k == 0 || k == 4 || k == 8) ? 1.0f : 0.0f;
            const float a = vlo ? s[olo + k] : idv;
            const float b = vhi ? s[ohi + k] : idv;
            R[k] = f2pack(a, b);
        }
    }
    __syncwarp();

    const u64 M0 = f2pack(m0, m0), M1 = f2pack(m1, m1), M2 = f2pack(m2, m2);
    const u64 M3 = f2pack(m3, m3), M4 = f2pack(m4, m4), M5 = f2pack(m5, m5);
    const u64 M6 = f2pack(m6, m6), M7 = f2pack(m7, m7), M8 = f2pack(m8, m8);

    P2 X;
    X.x0 = f2fma(R[0], M0, f2fma(R[1], M3, f2mul(R[2], M6)));
    X.x1 = f2fma(R[0], M1, f2fma(R[1], M4, f2mul(R[2], M7)));
    X.x2 = f2fma(R[0], M2, f2fma(R[1], M5, f2mul(R[2], M8)));
    X.x3 = f2fma(R[3], M0, f2fma(R[4], M3, f2mul(R[5], M6)));
    X.x4 = f2fma(R[3], M1, f2fma(R[4], M4, f2mul(R[5], M7)));
    X.x5 = f2fma(R[3], M2, f2fma(R[4], M5, f2mul(R[5], M8)));
    X.x6 = f2fma(R[6], M0, f2fma(R[7], M3, f2mul(R[8], M6)));
    X.x7 = f2fma(R[6], M1, f2fma(R[7], M4, f2mul(R[8], M7)));
    X.x8 = f2fma(R[6], M2, f2fma(R[7], M5, f2mul(R[8], M8)));

    // ---- head: 3 cheap det-scaled steps ----
    #pragma unroll
    for (int it = 0; it < 3; ++it) step_scaled(X);

    // ---- tail: plain Newton, free test-after-step, per-warp exit ----
    #pragma unroll 1
    for (int it = 0; it < 9; ++it) {
        const bool ok = step_plain(X);
        if (__all_sync(0xffffffffu, ok)) break;
    }

    // ---- scatter to smem, cooperative coalesced store ----
    {
        const int olo = 2 * tid * 9, ohi = olo + 9;
        float a, b;
        f2unpack(X.x0, a, b); s[olo + 0] = a; s[ohi + 0] = b;
        f2unpack(X.x1, a, b); s[olo + 1] = a; s[ohi + 1] = b;
        f2unpack(X.x2, a, b); s[olo + 2] = a; s[ohi + 2] = b;
        f2unpack(X.x3, a, b); s[olo + 3] = a; s[ohi + 3] = b;
        f2unpack(X.x4, a, b); s[olo + 4] = a; s[ohi + 4] = b;
        f2unpack(X.x5, a, b); s[olo + 5] = a; s[ohi + 5] = b;
        f2unpack(X.x6, a, b); s[olo + 6] = a; s[ohi + 6] = b;
        f2unpack(X.x7, a, b); s[olo + 7] = a; s[ohi + 7] = b;
        f2unpack(X.x8, a, b); s[olo + 8] = a; s[ohi + 8] = b;
    }
    __syncwarp();
    {
        float* g = out + (size_t)base * 9;
        const int nv = nflt >> 2;
        const float4* s4 = reinterpret_cast<const float4*>(s);
        float4* g4 = reinterpret_cast<float4*>(g);
        for (int i = tid; i < nv; i += TPB) g4[i] = s4[i];
        for (int i = (nv << 2) + tid; i < nflt; i += TPB) g[i] = s[i];
    }

    for (int i = tid; i < nmat; i += TPB) logdet[base + i] = 0.0f;
}

__global__ void zero_tail_kernel(float* __restrict__ p, long long n)
{
    long long i = (long long)blockIdx.x * blockDim.x + threadIdx.x;
    if (i < n) p[i] = 0.0f;
}

extern "C" void kernel_launch(void* const* d_in, const int* in_sizes, int n_in,
                              void* d_out, int out_size)
{
    const float* rot = (const float*)d_in[0];
    const float* mat = (const float*)d_in[1];
    float* out = (float*)d_out;

    const int N = in_sizes[0] / 9;
    float* logdet = out + (size_t)N * 9;

    const int mats_per_block = TPB * 2;
    const int blocks = (N + mats_per_block - 1) / mats_per_block;
    polar_w2_kernel<<<blocks, TPB>>>(rot, mat, out, logdet, N);

    const long long used = 10LL * N;
    if ((long long)out_size > used) {
        const long long extra = (long long)out_size - used;
        const int zb = (int)((extra + 255) / 256);
        zero_tail_kernel<<<zb, 256>>>(out + used, extra);
    }
}